// round 8
// baseline (speedup 1.0000x reference)
#include <cuda_runtime.h>
#include <cstdint>

#define NFULL 0xffffffffu

namespace {
constexpr int BB   = 8;
constexpr int SS   = 4096;
constexpr int DM   = 256;
constexpr int DI   = 512;
constexpr int DS   = 16;
constexpr int MT   = BB * SS;   // 32768 tokens
constexpr int NCH  = 64;        // scan chunks
constexpr int CL   = SS / NCH;  // 64 steps per chunk
constexpr float EPSV = 1e-5f;
}

// ------------------------------------------------------------------ scratch
__device__ __align__(16) float g_x    [MT * DM];   // residual stream
__device__ __align__(16) float g_xn   [MT * DM];   // layernorm output
__device__ __align__(16) float g_xp   [MT * DI];   // inproj half 1
__device__ __align__(16) float g_z    [MT * DI];   // inproj half 2 (gate)
__device__ __align__(16) float g_xc   [MT * DI];   // conv+silu output
__device__ __align__(16) float g_dt   [MT * DI];   // running cumsum of dt
__device__ __align__(16) float g_y    [MT * DI];   // scan output (gated by scan3)
__device__ __align__(16) float g_Bm   [MT * DS];
__device__ __align__(16) float g_Cm   [MT * DS];
__device__ __align__(16) float g_dtraw[MT];
__device__ __align__(16) float g_hf   [BB * NCH * DS * DI];
__device__ __align__(16) float g_h0   [BB * NCH * DS * DI];

__device__ __forceinline__ float siluf(float x) {
    return x / (1.f + __expf(-x));
}

__global__ void k_nop() {
    if (threadIdx.x == 0) g_dtraw[0] = 0.f;  // overwritten by k_cxp before use
}

// ----------------------------------------- fused inproj + layernorm (layer 0)
__global__ void k_inln(const float* __restrict__ z,
                       const float* __restrict__ w,
                       const float* __restrict__ ipb,
                       const float* __restrict__ g,
                       const float* __restrict__ b) {
    int warp = (blockIdx.x * blockDim.x + threadIdx.x) >> 5;
    int lane = threadIdx.x & 31;
    if (warp >= MT) return;
    float4 zv = *reinterpret_cast<const float4*>(z + (size_t)warp * 4);
    float v[8];
    float s = 0.f;
#pragma unroll
    for (int i = 0; i < 8; i++) {
        int c = i * 32 + lane;
        float4 wv = *reinterpret_cast<const float4*>(w + (size_t)c * 4);
        v[i] = ipb[c] + zv.x * wv.x + zv.y * wv.y + zv.z * wv.z + zv.w * wv.w;
        g_x[(size_t)warp * DM + c] = v[i];
        s += v[i];
    }
#pragma unroll
    for (int o = 16; o; o >>= 1) s += __shfl_xor_sync(NFULL, s, o);
    float mu = s * (1.f / DM);
    float q = 0.f;
#pragma unroll
    for (int i = 0; i < 8; i++) { float d = v[i] - mu; q += d * d; }
#pragma unroll
    for (int o = 16; o; o >>= 1) q += __shfl_xor_sync(NFULL, q, o);
    float r = rsqrtf(q * (1.f / DM) + EPSV);
#pragma unroll
    for (int i = 0; i < 8; i++) {
        int c = i * 32 + lane;
        g_xn[(size_t)warp * DM + c] = (v[i] - mu) * r * g[c] + b[c];
    }
}

// ----------------------------------------------------------------- layernorm
__global__ void k_ln(const float* __restrict__ g, const float* __restrict__ b) {
    int warp = (blockIdx.x * blockDim.x + threadIdx.x) >> 5;
    int lane = threadIdx.x & 31;
    if (warp >= MT) return;
    const float* xr = g_x + (size_t)warp * DM;
    float v[8];
    float s = 0.f;
#pragma unroll
    for (int i = 0; i < 8; i++) { v[i] = xr[i * 32 + lane]; s += v[i]; }
#pragma unroll
    for (int o = 16; o; o >>= 1) s += __shfl_xor_sync(NFULL, s, o);
    float mu = s * (1.f / DM);
    float q = 0.f;
#pragma unroll
    for (int i = 0; i < 8; i++) { float d = v[i] - mu; q += d * d; }
#pragma unroll
    for (int o = 16; o; o >>= 1) q += __shfl_xor_sync(NFULL, q, o);
    float r = rsqrtf(q * (1.f / DM) + EPSV);
    float* out = g_xn + (size_t)warp * DM;
#pragma unroll
    for (int i = 0; i < 8; i++) {
        int c = i * 32 + lane;
        out[c] = (v[i] - mu) * r * g[c] + b[c];
    }
}

// ------------------------------------------------------------------- GEMM v3
// (reverted R6 scalar version; gate is pre-applied to g_y by scan3)
// C(MT x N) = A(MT x K) * W^T. 128x128 tile, BK=16, 256 threads, 8x8 acc,
// double-buffered smem, one barrier per 16-k chunk, 2 CTAs/SM.
// MODE 0: A = g_xn (K=256), N=1024 -> cols<512 to g_xp, cols>=512 to g_z
// MODE 1: A = g_y (gated, K=512), N=256 -> g_x += result (residual)
template <int MODE>
__global__ __launch_bounds__(256, 2)
void k_gemm(const float* __restrict__ W) {
    constexpr int K = (MODE == 0) ? DM : DI;
    constexpr int BK = 16;
    __shared__ float As[2][BK][128];
    __shared__ float Bs[2][BK][128];
    const int tid = threadIdx.x;
    const int mBase = blockIdx.y * 128;
    const int nBase = blockIdx.x * 128;
    const int tx = tid & 15;
    const int ty = tid >> 4;
    const int lr = tid >> 1;
    const int lc = (tid & 1) * 8;

    const float* Aptr = (MODE == 0) ? g_xn : g_y;
    const float* aRow = Aptr + (size_t)(mBase + lr) * K + lc;
    const float* bRow = W + (size_t)(nBase + lr) * K + lc;

    float4 pa0, pa1, pb0, pb1;
    auto loadAB = [&](int k0) {
        pa0 = *reinterpret_cast<const float4*>(aRow + k0);
        pa1 = *reinterpret_cast<const float4*>(aRow + k0 + 4);
        pb0 = *reinterpret_cast<const float4*>(bRow + k0);
        pb1 = *reinterpret_cast<const float4*>(bRow + k0 + 4);
    };
    auto store = [&](int st) {
        As[st][lc + 0][lr] = pa0.x; As[st][lc + 1][lr] = pa0.y;
        As[st][lc + 2][lr] = pa0.z; As[st][lc + 3][lr] = pa0.w;
        As[st][lc + 4][lr] = pa1.x; As[st][lc + 5][lr] = pa1.y;
        As[st][lc + 6][lr] = pa1.z; As[st][lc + 7][lr] = pa1.w;
        Bs[st][lc + 0][lr] = pb0.x; Bs[st][lc + 1][lr] = pb0.y;
        Bs[st][lc + 2][lr] = pb0.z; Bs[st][lc + 3][lr] = pb0.w;
        Bs[st][lc + 4][lr] = pb1.x; Bs[st][lc + 5][lr] = pb1.y;
        Bs[st][lc + 6][lr] = pb1.z; Bs[st][lc + 7][lr] = pb1.w;
    };

    float acc[8][8];
#pragma unroll
    for (int i = 0; i < 8; i++)
#pragma unroll
        for (int j = 0; j < 8; j++) acc[i][j] = 0.f;

    loadAB(0);
    store(0);
    __syncthreads();

    for (int k0 = 0; k0 < K; k0 += BK) {
        const int cur = (k0 >> 4) & 1;
        const bool more = (k0 + BK) < K;
        if (more) loadAB(k0 + BK);
#pragma unroll
        for (int kk = 0; kk < BK; kk++) {
            float4 a0 = *reinterpret_cast<const float4*>(&As[cur][kk][ty * 4]);
            float4 a1 = *reinterpret_cast<const float4*>(&As[cur][kk][64 + ty * 4]);
            float4 b0 = *reinterpret_cast<const float4*>(&Bs[cur][kk][tx * 4]);
            float4 b1 = *reinterpret_cast<const float4*>(&Bs[cur][kk][64 + tx * 4]);
            const float af[8] = {a0.x, a0.y, a0.z, a0.w, a1.x, a1.y, a1.z, a1.w};
            const float bf[8] = {b0.x, b0.y, b0.z, b0.w, b1.x, b1.y, b1.z, b1.w};
#pragma unroll
            for (int i = 0; i < 8; i++)
#pragma unroll
                for (int j = 0; j < 8; j++)
                    acc[i][j] = fmaf(af[i], bf[j], acc[i][j]);
        }
        if (more) store(cur ^ 1);
        __syncthreads();
    }

#pragma unroll
    for (int i = 0; i < 8; i++) {
        int row = mBase + ((i < 4) ? (ty * 4 + i) : (64 + ty * 4 + i - 4));
#pragma unroll
        for (int jh = 0; jh < 2; jh++) {
            int n0 = nBase + jh * 64 + tx * 4;
            float4 v = make_float4(acc[i][jh * 4], acc[i][jh * 4 + 1],
                                   acc[i][jh * 4 + 2], acc[i][jh * 4 + 3]);
            if (MODE == 0) {
                float* dst = (n0 < DI) ? (g_xp + (size_t)row * DI + n0)
                                       : (g_z  + (size_t)row * DI + n0 - DI);
                *reinterpret_cast<float4*>(dst) = v;
            } else {
                float4* p = reinterpret_cast<float4*>(g_x + (size_t)row * DM + n0);
                float4 o = *p;
                o.x += v.x; o.y += v.y; o.z += v.z; o.w += v.w;
                *p = o;
            }
        }
    }
}

// ---------------------------------- fused depthwise conv + SiLU + xproj GEMV
// v2: lane owns d in [16*lane, 16*lane+16) -> all Wx / xp / cw accesses are
// LDG.128 and fully coalesced per warp; reduced results land on lane==n so
// B/C stores are two coalesced 64B line writes.
__global__ void k_cxp(const float* __restrict__ cw, const float* __restrict__ cb,
                      const float* __restrict__ Wx) {
    int warp = (blockIdx.x * blockDim.x + threadIdx.x) >> 5;
    int lane = threadIdx.x & 31;
    if (warp >= MT) return;
    const int t = warp & (SS - 1);
    const int d0 = lane * 16;

    float v[16];
#pragma unroll
    for (int q = 0; q < 4; q++) {
        const int d = d0 + q * 4;
        float4 acc = *reinterpret_cast<const float4*>(cb + d);
        float4 w0 = *reinterpret_cast<const float4*>(cw + (size_t)(d + 0) * 4);
        float4 w1 = *reinterpret_cast<const float4*>(cw + (size_t)(d + 1) * 4);
        float4 w2 = *reinterpret_cast<const float4*>(cw + (size_t)(d + 2) * 4);
        float4 w3 = *reinterpret_cast<const float4*>(cw + (size_t)(d + 3) * 4);
#pragma unroll
        for (int j = 0; j < 4; j++) {
            if (t - 3 + j >= 0) {
                float4 xv = *reinterpret_cast<const float4*>(
                    g_xp + (size_t)(warp + j - 3) * DI + d);
                acc.x = fmaf(xv.x, (&w0.x)[j], acc.x);
                acc.y = fmaf(xv.y, (&w1.x)[j], acc.y);
                acc.z = fmaf(xv.z, (&w2.x)[j], acc.z);
                acc.w = fmaf(xv.w, (&w3.x)[j], acc.w);
            }
        }
        acc.x = siluf(acc.x); acc.y = siluf(acc.y);
        acc.z = siluf(acc.z); acc.w = siluf(acc.w);
        *reinterpret_cast<float4*>(g_xc + (size_t)warp * DI + d) = acc;
        v[q * 4 + 0] = acc.x; v[q * 4 + 1] = acc.y;
        v[q * 4 + 2] = acc.z; v[q * 4 + 3] = acc.w;
    }

    float rb = 0.f, rc = 0.f, rd = 0.f;
#pragma unroll
    for (int n = 0; n < 2 * DS + 1; n++) {
        const float* w = Wx + (size_t)n * DI + d0;
        float acc = 0.f;
#pragma unroll
        for (int q = 0; q < 4; q++) {
            float4 wv = *reinterpret_cast<const float4*>(w + q * 4);
            acc = fmaf(v[q * 4 + 0], wv.x, acc);
            acc = fmaf(v[q * 4 + 1], wv.y, acc);
            acc = fmaf(v[q * 4 + 2], wv.z, acc);
            acc = fmaf(v[q * 4 + 3], wv.w, acc);
        }
#pragma unroll
        for (int o = 16; o; o >>= 1) acc += __shfl_xor_sync(NFULL, acc, o);
        if (n < DS)          { if (lane == n)          rb = acc; }
        else if (n < 2 * DS) { if (lane == n - DS + 16) rc = acc; }
        else                 rd = acc;
    }
    if (lane < 16) g_Bm[(size_t)warp * DS + lane] = rb;
    else           g_Cm[(size_t)warp * DS + lane - 16] = rc;
    if (lane == 0) g_dtraw[warp] = rd;
}

// w^(s+1) powers via multiply tree
__device__ __forceinline__ void powers16(float w, float* p) {
    p[0] = w;
    p[1] = w * w;
    p[2] = p[1] * w;    p[3]  = p[1] * p[1];
    p[4] = p[3] * w;    p[5]  = p[3] * p[1];
    p[6] = p[3] * p[2]; p[7]  = p[3] * p[3];
    p[8] = p[7] * w;    p[9]  = p[7] * p[1];
    p[10] = p[7] * p[2]; p[11] = p[7] * p[3];
    p[12] = p[7] * p[4]; p[13] = p[7] * p[5];
    p[14] = p[7] * p[6]; p[15] = p[7] * p[7];
}

// ------------------------------------------- scan phase 1: per-chunk scan
// fast softplus: w = exp(-softplus(xr)) = 1/(1+exp(xr)); dtv = -log(w)
__global__ __launch_bounds__(128)
void k_scan1(const float* __restrict__ dw, const float* __restrict__ db) {
    __shared__ float Bs[CL * DS], Cs[CL * DS], dts[CL];
    const int d = blockIdx.x * 128 + threadIdx.x;
    const int c = blockIdx.y, b = blockIdx.z;
    const int tid = threadIdx.x;
    const size_t baseT = (size_t)b * SS + c * CL;

    const float4* Bsrc = reinterpret_cast<const float4*>(g_Bm + baseT * DS);
    const float4* Csrc = reinterpret_cast<const float4*>(g_Cm + baseT * DS);
#pragma unroll
    for (int i = 0; i < CL * DS / 4 / 128; i++) {
        reinterpret_cast<float4*>(Bs)[tid + i * 128] = Bsrc[tid + i * 128];
        reinterpret_cast<float4*>(Cs)[tid + i * 128] = Csrc[tid + i * 128];
    }
    if (tid < CL / 4)
        reinterpret_cast<float4*>(dts)[tid] =
            reinterpret_cast<const float4*>(g_dtraw + baseT)[tid];
    __syncthreads();

    const float dwv = dw[d], dbv = db[d];
    float h[DS];
#pragma unroll
    for (int s = 0; s < DS; s++) h[s] = 0.f;
    float cum = 0.f;

    for (int t = 0; t < CL; t++) {
        float xr = dts[t] * dwv + dbv;
        xr = fminf(fmaxf(xr, -30.f), 30.f);
        float e = __expf(xr);
        float w = __frcp_rn(1.f + e);      // exp(-dt)
        float dtv = -__logf(w);            // softplus(xr)
        float x = g_xc[(baseT + t) * DI + d];
        cum += dtv;
        g_dt[(baseT + t) * DI + d] = cum;
        float u = dtv * x;
        float p[DS];
        powers16(w, p);
        float y = 0.f;
#pragma unroll
        for (int s = 0; s < DS; s++) {
            h[s] = fmaf(h[s], p[s], u * Bs[t * DS + s]);
            y = fmaf(h[s], Cs[t * DS + s], y);
        }
        g_y[(baseT + t) * DI + d] = y;
    }
#pragma unroll
    for (int s = 0; s < DS; s++)
        g_hf[((size_t)(b * NCH + c) * DS + s) * DI + d] = h[s];
}

// ------------------------------------------- scan phase 2: chain chunk states
__global__ void k_scan2() {
    int idx = blockIdx.x * blockDim.x + threadIdx.x;
    if (idx >= BB * DS * DI) return;
    const int d = idx % DI;
    const int s = (idx / DI) % DS;
    const int b = idx / (DI * DS);
    float h = 0.f;
    const float sf = (float)(s + 1);
    for (int c = 0; c < NCH; c++) {
        size_t o = ((size_t)(b * NCH + c) * DS + s) * DI + d;
        g_h0[o] = h;
        float cumt = g_dt[((size_t)b * SS + c * CL + CL - 1) * DI + d];
        h = fmaf(__expf(-sf * cumt), h, g_hf[o]);
    }
}

// --------------------- scan phase 3: h0 correction + SiLU gating (in place)
__global__ __launch_bounds__(128)
void k_scan3() {
    __shared__ float Cs[CL * DS];
    const int c = blockIdx.y;
    const int d = blockIdx.x * 128 + threadIdx.x;
    const int b = blockIdx.z;
    const int tid = threadIdx.x;
    const size_t baseT = (size_t)b * SS + c * CL;

    if (c > 0) {
        const float4* Csrc = reinterpret_cast<const float4*>(g_Cm + baseT * DS);
#pragma unroll
        for (int i = 0; i < CL * DS / 4 / 128; i++)
            reinterpret_cast<float4*>(Cs)[tid + i * 128] = Csrc[tid + i * 128];
        __syncthreads();

        float h0[DS];
#pragma unroll
        for (int s = 0; s < DS; s++)
            h0[s] = g_h0[((size_t)(b * NCH + c) * DS + s) * DI + d];

        for (int t = 0; t < CL; t++) {
            size_t idx = (baseT + t) * DI + d;
            float cum = g_dt[idx];
            float w = __expf(-cum);
            float p[DS];
            powers16(w, p);
            float y = g_y[idx];
#pragma unroll
            for (int s = 0; s < DS; s++)
                y = fmaf(h0[s] * p[s], Cs[t * DS + s], y);
            g_y[idx] = y * siluf(g_z[idx]);
        }
    } else {
        for (int t = 0; t < CL; t++) {
            size_t idx = (baseT + t) * DI + d;
            g_y[idx] = g_y[idx] * siluf(g_z[idx]);
        }
    }
}

// ---------------------------------------------------------- final LN + head
__global__ void k_final(const float* __restrict__ g, const float* __restrict__ b,
                        const float* __restrict__ ow, const float* __restrict__ ob,
                        float* __restrict__ out) {
    int warp = (blockIdx.x * blockDim.x + threadIdx.x) >> 5;
    int lane = threadIdx.x & 31;
    if (warp >= MT) return;
    const float* xr = g_x + (size_t)warp * DM;
    float v[8];
    float s = 0.f;
#pragma unroll
    for (int i = 0; i < 8; i++) { v[i] = xr[i * 32 + lane]; s += v[i]; }
#pragma unroll
    for (int o = 16; o; o >>= 1) s += __shfl_xor_sync(NFULL, s, o);
    float mu = s * (1.f / DM);
    float q = 0.f;
#pragma unroll
    for (int i = 0; i < 8; i++) { float d = v[i] - mu; q += d * d; }
#pragma unroll
    for (int o = 16; o; o >>= 1) q += __shfl_xor_sync(NFULL, q, o);
    float r = rsqrtf(q * (1.f / DM) + EPSV);
    float a0 = 0.f, a1 = 0.f;
#pragma unroll
    for (int i = 0; i < 8; i++) {
        int c = i * 32 + lane;
        float xn = (v[i] - mu) * r * g[c] + b[c];
        a0 += xn * ow[c];
        a1 += xn * ow[DM + c];
    }
#pragma unroll
    for (int o = 16; o; o >>= 1) {
        a0 += __shfl_xor_sync(NFULL, a0, o);
        a1 += __shfl_xor_sync(NFULL, a1, o);
    }
    if (lane == 0) {
        out[(size_t)warp * 2 + 0] = a0 + ob[0];
        out[(size_t)warp * 2 + 1] = a1 + ob[1];
    }
}

// ---------------------------------------------------------------------------
extern "C" void kernel_launch(void* const* d_in, const int* in_sizes, int n_in,
                              void* d_out, int out_size) {
    (void)in_sizes; (void)n_in; (void)out_size;
    const float* z_seq     = (const float*)d_in[0];
    const float* ip_w      = (const float*)d_in[1];
    const float* ip_b      = (const float*)d_in[2];
    const float* norm_g    = (const float*)d_in[3];
    const float* norm_b    = (const float*)d_in[4];
    const float* inproj_w  = (const float*)d_in[5];
    const float* conv_w    = (const float*)d_in[6];
    const float* conv_b    = (const float*)d_in[7];
    const float* xproj_w   = (const float*)d_in[8];
    const float* dt_w      = (const float*)d_in[9];
    const float* dt_b      = (const float*)d_in[10];
    const float* outproj_w = (const float*)d_in[11];
    const float* onorm_g   = (const float*)d_in[12];
    const float* onorm_b   = (const float*)d_in[13];
    const float* op_w      = (const float*)d_in[14];
    const float* op_b      = (const float*)d_in[15];
    float* out = (float*)d_out;

    k_nop<<<1, 32>>>();                                           // launch 1
    k_inln<<<MT / 8, 256>>>(z_seq, ip_w, ip_b, norm_g, norm_b);   // launch 2

    for (int l = 0; l < 2; l++) {
        if (l > 0)
            k_ln<<<MT / 8, 256>>>(norm_g + l * DM, norm_b + l * DM);
        k_gemm<0><<<dim3(2 * DI / 128, MT / 128), 256>>>(         // l=0: launch 3
            inproj_w + (size_t)l * 2 * DI * DM);
        k_cxp<<<MT / 8, 256>>>(conv_w + (size_t)l * DI * 4,       // l=0: launch 4 <- profiled
                               conv_b + (size_t)l * DI,
                               xproj_w + (size_t)l * (2 * DS + 1) * DI);
        k_scan1<<<dim3(DI / 128, NCH, BB), 128>>>(dt_w + (size_t)l * DI,
                                                  dt_b + (size_t)l * DI);
        k_scan2<<<BB * DS * DI / 256, 256>>>();
        k_scan3<<<dim3(DI / 128, NCH, BB), 128>>>();
        k_gemm<1><<<dim3(DM / 128, MT / 128), 256>>>(
            outproj_w + (size_t)l * DM * DI);
    }

    k_final<<<MT / 8, 256>>>(onorm_g, onorm_b, op_w, op_b, out);
}

// round 9
// speedup vs baseline: 1.2592x; 1.2592x over previous
#include <cuda_runtime.h>
#include <cstdint>

#define NFULL 0xffffffffu

namespace {
constexpr int BB   = 8;
constexpr int SS   = 4096;
constexpr int DM   = 256;
constexpr int DI   = 512;
constexpr int DS   = 16;
constexpr int MT   = BB * SS;   // 32768 tokens
constexpr int NCH  = 64;        // scan chunks
constexpr int CL   = SS / NCH;  // 64 steps per chunk
constexpr float EPSV = 1e-5f;
}

// ------------------------------------------------------------------ scratch
__device__ __align__(16) float g_x    [MT * DM];   // residual stream
__device__ __align__(16) float g_xn   [MT * DM];   // layernorm output
__device__ __align__(16) float g_xp   [MT * DI];   // inproj half 1
__device__ __align__(16) float g_z    [MT * DI];   // inproj half 2 (gate)
__device__ __align__(16) float g_xc   [MT * DI];   // conv+silu output
__device__ __align__(16) float g_dt   [MT * DI];   // running cumsum of dt
__device__ __align__(16) float g_y    [MT * DI];   // scan output (gated by scan3)
__device__ __align__(16) float g_Bm   [MT * DS];
__device__ __align__(16) float g_Cm   [MT * DS];
__device__ __align__(16) float g_dtraw[MT];
__device__ __align__(16) float g_hf   [BB * NCH * DS * DI];
__device__ __align__(16) float g_h0   [BB * NCH * DS * DI];

__device__ __forceinline__ float siluf(float x) {
    return x / (1.f + __expf(-x));
}

__global__ void k_nop() {
    if (threadIdx.x == 0) g_dtraw[0] = 0.f;  // overwritten by k_cxp before use
}

// ----------------------------------------- fused inproj + layernorm (layer 0)
__global__ void k_inln(const float* __restrict__ z,
                       const float* __restrict__ w,
                       const float* __restrict__ ipb,
                       const float* __restrict__ g,
                       const float* __restrict__ b) {
    int warp = (blockIdx.x * blockDim.x + threadIdx.x) >> 5;
    int lane = threadIdx.x & 31;
    if (warp >= MT) return;
    float4 zv = *reinterpret_cast<const float4*>(z + (size_t)warp * 4);
    float v[8];
    float s = 0.f;
#pragma unroll
    for (int i = 0; i < 8; i++) {
        int c = i * 32 + lane;
        float4 wv = *reinterpret_cast<const float4*>(w + (size_t)c * 4);
        v[i] = ipb[c] + zv.x * wv.x + zv.y * wv.y + zv.z * wv.z + zv.w * wv.w;
        g_x[(size_t)warp * DM + c] = v[i];
        s += v[i];
    }
#pragma unroll
    for (int o = 16; o; o >>= 1) s += __shfl_xor_sync(NFULL, s, o);
    float mu = s * (1.f / DM);
    float q = 0.f;
#pragma unroll
    for (int i = 0; i < 8; i++) { float d = v[i] - mu; q += d * d; }
#pragma unroll
    for (int o = 16; o; o >>= 1) q += __shfl_xor_sync(NFULL, q, o);
    float r = rsqrtf(q * (1.f / DM) + EPSV);
#pragma unroll
    for (int i = 0; i < 8; i++) {
        int c = i * 32 + lane;
        g_xn[(size_t)warp * DM + c] = (v[i] - mu) * r * g[c] + b[c];
    }
}

// ----------------------------------------------------------------- layernorm
__global__ void k_ln(const float* __restrict__ g, const float* __restrict__ b) {
    int warp = (blockIdx.x * blockDim.x + threadIdx.x) >> 5;
    int lane = threadIdx.x & 31;
    if (warp >= MT) return;
    const float* xr = g_x + (size_t)warp * DM;
    float v[8];
    float s = 0.f;
#pragma unroll
    for (int i = 0; i < 8; i++) { v[i] = xr[i * 32 + lane]; s += v[i]; }
#pragma unroll
    for (int o = 16; o; o >>= 1) s += __shfl_xor_sync(NFULL, s, o);
    float mu = s * (1.f / DM);
    float q = 0.f;
#pragma unroll
    for (int i = 0; i < 8; i++) { float d = v[i] - mu; q += d * d; }
#pragma unroll
    for (int o = 16; o; o >>= 1) q += __shfl_xor_sync(NFULL, q, o);
    float r = rsqrtf(q * (1.f / DM) + EPSV);
    float* out = g_xn + (size_t)warp * DM;
#pragma unroll
    for (int i = 0; i < 8; i++) {
        int c = i * 32 + lane;
        out[c] = (v[i] - mu) * r * g[c] + b[c];
    }
}

// ------------------------------------------------------------------- GEMM
// C(MT x N) = A(MT x K) * W^T. BK=16, 256 threads, double-buffered smem,
// one barrier per 16-k chunk, 2 CTAs/SM.
// MODE 0: tile 128x128, 8x8 acc. A=g_xn (K=256), N=1024 -> g_xp / g_z.
// MODE 1: tile 128x64, 8x4 acc (more blocks -> less wave tail).
//         A=g_y (gated, K=512), N=256 -> g_x += result (residual).
template <int MODE>
__global__ __launch_bounds__(256, 2)
void k_gemm(const float* __restrict__ W) {
    constexpr int K  = (MODE == 0) ? DM : DI;
    constexpr int TN = (MODE == 0) ? 128 : 64;
    constexpr int BK = 16;
    __shared__ float As[2][BK][128];
    __shared__ float Bs[2][BK][TN];
    const int tid = threadIdx.x;
    const int mBase = blockIdx.y * 128;
    const int nBase = blockIdx.x * TN;
    const int tx = tid & 15;
    const int ty = tid >> 4;
    // A loader: 128 rows x 16 k, 8 floats per thread
    const int lr = tid >> 1;
    const int lc = (tid & 1) * 8;
    // B loader: TN rows x 16 k
    const int lrB = (MODE == 0) ? lr : (tid >> 2);
    const int lcB = (MODE == 0) ? lc : ((tid & 3) * 4);

    const float* Aptr = (MODE == 0) ? g_xn : g_y;
    const float* aRow = Aptr + (size_t)(mBase + lr) * K + lc;
    const float* bRow = W + (size_t)(nBase + lrB) * K + lcB;

    float4 pa0, pa1, pb0, pb1;
    auto loadAB = [&](int k0) {
        pa0 = *reinterpret_cast<const float4*>(aRow + k0);
        pa1 = *reinterpret_cast<const float4*>(aRow + k0 + 4);
        pb0 = *reinterpret_cast<const float4*>(bRow + k0);
        if (MODE == 0)
            pb1 = *reinterpret_cast<const float4*>(bRow + k0 + 4);
    };
    auto store = [&](int st) {
        As[st][lc + 0][lr] = pa0.x; As[st][lc + 1][lr] = pa0.y;
        As[st][lc + 2][lr] = pa0.z; As[st][lc + 3][lr] = pa0.w;
        As[st][lc + 4][lr] = pa1.x; As[st][lc + 5][lr] = pa1.y;
        As[st][lc + 6][lr] = pa1.z; As[st][lc + 7][lr] = pa1.w;
        Bs[st][lcB + 0][lrB] = pb0.x; Bs[st][lcB + 1][lrB] = pb0.y;
        Bs[st][lcB + 2][lrB] = pb0.z; Bs[st][lcB + 3][lrB] = pb0.w;
        if (MODE == 0) {
            Bs[st][lcB + 4][lrB] = pb1.x; Bs[st][lcB + 5][lrB] = pb1.y;
            Bs[st][lcB + 6][lrB] = pb1.z; Bs[st][lcB + 7][lrB] = pb1.w;
        }
    };

    constexpr int NJ = TN / 16;   // 8 or 4 cols per thread
    float acc[8][NJ];
#pragma unroll
    for (int i = 0; i < 8; i++)
#pragma unroll
        for (int j = 0; j < NJ; j++) acc[i][j] = 0.f;

    loadAB(0);
    store(0);
    __syncthreads();

    for (int k0 = 0; k0 < K; k0 += BK) {
        const int cur = (k0 >> 4) & 1;
        const bool more = (k0 + BK) < K;
        if (more) loadAB(k0 + BK);
#pragma unroll
        for (int kk = 0; kk < BK; kk++) {
            float4 a0 = *reinterpret_cast<const float4*>(&As[cur][kk][ty * 4]);
            float4 a1 = *reinterpret_cast<const float4*>(&As[cur][kk][64 + ty * 4]);
            const float af[8] = {a0.x, a0.y, a0.z, a0.w, a1.x, a1.y, a1.z, a1.w};
            float bf[NJ];
            {
                float4 b0 = *reinterpret_cast<const float4*>(&Bs[cur][kk][tx * 4]);
                bf[0] = b0.x; bf[1] = b0.y; bf[2] = b0.z; bf[3] = b0.w;
                if (MODE == 0) {
                    float4 b1 = *reinterpret_cast<const float4*>(&Bs[cur][kk][64 + tx * 4]);
                    bf[4] = b1.x; bf[5] = b1.y; bf[6] = b1.z; bf[7] = b1.w;
                }
            }
#pragma unroll
            for (int i = 0; i < 8; i++)
#pragma unroll
                for (int j = 0; j < NJ; j++)
                    acc[i][j] = fmaf(af[i], bf[j], acc[i][j]);
        }
        if (more) store(cur ^ 1);
        __syncthreads();
    }

#pragma unroll
    for (int i = 0; i < 8; i++) {
        int row = mBase + ((i < 4) ? (ty * 4 + i) : (64 + ty * 4 + i - 4));
#pragma unroll
        for (int jh = 0; jh < NJ / 4; jh++) {
            int n0 = nBase + jh * 64 + tx * 4;
            float4 v = make_float4(acc[i][jh * 4], acc[i][jh * 4 + 1],
                                   acc[i][jh * 4 + 2], acc[i][jh * 4 + 3]);
            if (MODE == 0) {
                float* dst = (n0 < DI) ? (g_xp + (size_t)row * DI + n0)
                                       : (g_z  + (size_t)row * DI + n0 - DI);
                *reinterpret_cast<float4*>(dst) = v;
            } else {
                float4* p = reinterpret_cast<float4*>(g_x + (size_t)row * DM + n0);
                float4 o = *p;
                o.x += v.x; o.y += v.y; o.z += v.z; o.w += v.w;
                *p = o;
            }
        }
    }
}

// ---------------------------------- fused depthwise conv + SiLU + xproj GEMV
// v1 layout (proven): lane handles d = i*32+lane -> 4B coalesced accesses.
__global__ void k_cxp(const float* __restrict__ cw, const float* __restrict__ cb,
                      const float* __restrict__ Wx) {
    int warp = (blockIdx.x * blockDim.x + threadIdx.x) >> 5;
    int lane = threadIdx.x & 31;
    if (warp >= MT) return;
    const int t = warp & (SS - 1);

    float v[16];
#pragma unroll
    for (int i = 0; i < 16; i++) {
        int d = i * 32 + lane;
        float acc = cb[d];
        float4 wv = *reinterpret_cast<const float4*>(cw + (size_t)d * 4);
#pragma unroll
        for (int j = 0; j < 4; j++) {
            int tt = t - 3 + j;
            if (tt >= 0)
                acc = fmaf(g_xp[(size_t)(warp + j - 3) * DI + d], (&wv.x)[j], acc);
        }
        v[i] = siluf(acc);
        g_xc[(size_t)warp * DI + d] = v[i];
    }

    for (int n = 0; n < 2 * DS + 1; n++) {
        const float* w = Wx + (size_t)n * DI;
        float acc = 0.f;
#pragma unroll
        for (int i = 0; i < 16; i++) acc = fmaf(v[i], w[i * 32 + lane], acc);
#pragma unroll
        for (int o = 16; o; o >>= 1) acc += __shfl_xor_sync(NFULL, acc, o);
        if (lane == 0) {
            if (n < DS)          g_Bm[(size_t)warp * DS + n] = acc;
            else if (n < 2 * DS) g_Cm[(size_t)warp * DS + n - DS] = acc;
            else                 g_dtraw[warp] = acc;
        }
    }
}

// w^(s+1) powers via multiply tree
__device__ __forceinline__ void powers16(float w, float* p) {
    p[0] = w;
    p[1] = w * w;
    p[2] = p[1] * w;    p[3]  = p[1] * p[1];
    p[4] = p[3] * w;    p[5]  = p[3] * p[1];
    p[6] = p[3] * p[2]; p[7]  = p[3] * p[3];
    p[8] = p[7] * w;    p[9]  = p[7] * p[1];
    p[10] = p[7] * p[2]; p[11] = p[7] * p[3];
    p[12] = p[7] * p[4]; p[13] = p[7] * p[5];
    p[14] = p[7] * p[6]; p[15] = p[7] * p[7];
}

// ------------------------------------------- scan phase 1: per-chunk scan
// fast softplus: w = exp(-softplus(xr)) = 1/(1+exp(xr)); dtv = -log(w)
__global__ __launch_bounds__(128)
void k_scan1(const float* __restrict__ dw, const float* __restrict__ db) {
    __shared__ float Bs[CL * DS], Cs[CL * DS], dts[CL];
    const int d = blockIdx.x * 128 + threadIdx.x;
    const int c = blockIdx.y, b = blockIdx.z;
    const int tid = threadIdx.x;
    const size_t baseT = (size_t)b * SS + c * CL;

    const float4* Bsrc = reinterpret_cast<const float4*>(g_Bm + baseT * DS);
    const float4* Csrc = reinterpret_cast<const float4*>(g_Cm + baseT * DS);
#pragma unroll
    for (int i = 0; i < CL * DS / 4 / 128; i++) {
        reinterpret_cast<float4*>(Bs)[tid + i * 128] = Bsrc[tid + i * 128];
        reinterpret_cast<float4*>(Cs)[tid + i * 128] = Csrc[tid + i * 128];
    }
    if (tid < CL / 4)
        reinterpret_cast<float4*>(dts)[tid] =
            reinterpret_cast<const float4*>(g_dtraw + baseT)[tid];
    __syncthreads();

    const float dwv = dw[d], dbv = db[d];
    float h[DS];
#pragma unroll
    for (int s = 0; s < DS; s++) h[s] = 0.f;
    float cum = 0.f;

    for (int t = 0; t < CL; t++) {
        float xr = dts[t] * dwv + dbv;
        xr = fminf(fmaxf(xr, -30.f), 30.f);
        float e = __expf(xr);
        float w = __frcp_rn(1.f + e);      // exp(-dt)
        float dtv = -__logf(w);            // softplus(xr)
        float x = g_xc[(baseT + t) * DI + d];
        cum += dtv;
        g_dt[(baseT + t) * DI + d] = cum;
        float u = dtv * x;
        float p[DS];
        powers16(w, p);
        float y = 0.f;
#pragma unroll
        for (int s = 0; s < DS; s++) {
            h[s] = fmaf(h[s], p[s], u * Bs[t * DS + s]);
            y = fmaf(h[s], Cs[t * DS + s], y);
        }
        g_y[(baseT + t) * DI + d] = y;
    }
#pragma unroll
    for (int s = 0; s < DS; s++)
        g_hf[((size_t)(b * NCH + c) * DS + s) * DI + d] = h[s];
}

// ------------------------------------------- scan phase 2: chain chunk states
__global__ void k_scan2() {
    int idx = blockIdx.x * blockDim.x + threadIdx.x;
    if (idx >= BB * DS * DI) return;
    const int d = idx % DI;
    const int s = (idx / DI) % DS;
    const int b = idx / (DI * DS);
    float h = 0.f;
    const float sf = (float)(s + 1);
    for (int c = 0; c < NCH; c++) {
        size_t o = ((size_t)(b * NCH + c) * DS + s) * DI + d;
        g_h0[o] = h;
        float cumt = g_dt[((size_t)b * SS + c * CL + CL - 1) * DI + d];
        h = fmaf(__expf(-sf * cumt), h, g_hf[o]);
    }
}

// --------------------- scan phase 3: h0 correction + SiLU gating (in place)
__global__ __launch_bounds__(128)
void k_scan3() {
    __shared__ float Cs[CL * DS];
    const int c = blockIdx.y;
    const int d = blockIdx.x * 128 + threadIdx.x;
    const int b = blockIdx.z;
    const int tid = threadIdx.x;
    const size_t baseT = (size_t)b * SS + c * CL;

    if (c > 0) {
        const float4* Csrc = reinterpret_cast<const float4*>(g_Cm + baseT * DS);
#pragma unroll
        for (int i = 0; i < CL * DS / 4 / 128; i++)
            reinterpret_cast<float4*>(Cs)[tid + i * 128] = Csrc[tid + i * 128];
        __syncthreads();

        float h0[DS];
#pragma unroll
        for (int s = 0; s < DS; s++)
            h0[s] = g_h0[((size_t)(b * NCH + c) * DS + s) * DI + d];

        for (int t = 0; t < CL; t++) {
            size_t idx = (baseT + t) * DI + d;
            float cum = g_dt[idx];
            float w = __expf(-cum);
            float p[DS];
            powers16(w, p);
            float y = g_y[idx];
#pragma unroll
            for (int s = 0; s < DS; s++)
                y = fmaf(h0[s] * p[s], Cs[t * DS + s], y);
            g_y[idx] = y * siluf(g_z[idx]);
        }
    } else {
        for (int t = 0; t < CL; t++) {
            size_t idx = (baseT + t) * DI + d;
            g_y[idx] = g_y[idx] * siluf(g_z[idx]);
        }
    }
}

// ---------------------------------------------------------- final LN + head
__global__ void k_final(const float* __restrict__ g, const float* __restrict__ b,
                        const float* __restrict__ ow, const float* __restrict__ ob,
                        float* __restrict__ out) {
    int warp = (blockIdx.x * blockDim.x + threadIdx.x) >> 5;
    int lane = threadIdx.x & 31;
    if (warp >= MT) return;
    const float* xr = g_x + (size_t)warp * DM;
    float v[8];
    float s = 0.f;
#pragma unroll
    for (int i = 0; i < 8; i++) { v[i] = xr[i * 32 + lane]; s += v[i]; }
#pragma unroll
    for (int o = 16; o; o >>= 1) s += __shfl_xor_sync(NFULL, s, o);
    float mu = s * (1.f / DM);
    float q = 0.f;
#pragma unroll
    for (int i = 0; i < 8; i++) { float d = v[i] - mu; q += d * d; }
#pragma unroll
    for (int o = 16; o; o >>= 1) q += __shfl_xor_sync(NFULL, q, o);
    float r = rsqrtf(q * (1.f / DM) + EPSV);
    float a0 = 0.f, a1 = 0.f;
#pragma unroll
    for (int i = 0; i < 8; i++) {
        int c = i * 32 + lane;
        float xn = (v[i] - mu) * r * g[c] + b[c];
        a0 += xn * ow[c];
        a1 += xn * ow[DM + c];
    }
#pragma unroll
    for (int o = 16; o; o >>= 1) {
        a0 += __shfl_xor_sync(NFULL, a0, o);
        a1 += __shfl_xor_sync(NFULL, a1, o);
    }
    if (lane == 0) {
        out[(size_t)warp * 2 + 0] = a0 + ob[0];
        out[(size_t)warp * 2 + 1] = a1 + ob[1];
    }
}

// ---------------------------------------------------------------------------
extern "C" void kernel_launch(void* const* d_in, const int* in_sizes, int n_in,
                              void* d_out, int out_size) {
    (void)in_sizes; (void)n_in; (void)out_size;
    const float* z_seq     = (const float*)d_in[0];
    const float* ip_w      = (const float*)d_in[1];
    const float* ip_b      = (const float*)d_in[2];
    const float* norm_g    = (const float*)d_in[3];
    const float* norm_b    = (const float*)d_in[4];
    const float* inproj_w  = (const float*)d_in[5];
    const float* conv_w    = (const float*)d_in[6];
    const float* conv_b    = (const float*)d_in[7];
    const float* xproj_w   = (const float*)d_in[8];
    const float* dt_w      = (const float*)d_in[9];
    const float* dt_b      = (const float*)d_in[10];
    const float* outproj_w = (const float*)d_in[11];
    const float* onorm_g   = (const float*)d_in[12];
    const float* onorm_b   = (const float*)d_in[13];
    const float* op_w      = (const float*)d_in[14];
    const float* op_b      = (const float*)d_in[15];
    float* out = (float*)d_out;

    k_nop<<<1, 32>>>();                                           // launch 1
    k_inln<<<MT / 8, 256>>>(z_seq, ip_w, ip_b, norm_g, norm_b);   // launch 2

    for (int l = 0; l < 2; l++) {
        if (l > 0)
            k_ln<<<MT / 8, 256>>>(norm_g + l * DM, norm_b + l * DM);
        k_gemm<0><<<dim3(2 * DI / 128, MT / 128), 256>>>(         // l=0: launch 3
            inproj_w + (size_t)l * 2 * DI * DM);
        k_cxp<<<MT / 8, 256>>>(conv_w + (size_t)l * DI * 4,       // l=0: launch 4 <- profiled
                               conv_b + (size_t)l * DI,
                               xproj_w + (size_t)l * (2 * DS + 1) * DI);
        k_scan1<<<dim3(DI / 128, NCH, BB), 128>>>(dt_w + (size_t)l * DI,
                                                  dt_b + (size_t)l * DI);
        k_scan2<<<BB * DS * DI / 256, 256>>>();
        k_scan3<<<dim3(DI / 128, NCH, BB), 128>>>();
        k_gemm<1><<<dim3(DM / 64, MT / 128), 256>>>(
            outproj_w + (size_t)l * DM * DI);
    }

    k_final<<<MT / 8, 256>>>(onorm_g, onorm_b, op_w, op_b, out);
}

// round 10
// speedup vs baseline: 1.2603x; 1.0009x over previous
#include <cuda_runtime.h>
#include <cstdint>

#define NFULL 0xffffffffu

namespace {
constexpr int BB   = 8;
constexpr int SS   = 4096;
constexpr int DM   = 256;
constexpr int DI   = 512;
constexpr int DS   = 16;
constexpr int MT   = BB * SS;   // 32768 tokens
constexpr int NCH  = 64;        // scan chunks
constexpr int CL   = SS / NCH;  // 64 steps per chunk
constexpr float EPSV = 1e-5f;
}

// ------------------------------------------------------------------ scratch
__device__ __align__(16) float g_x    [MT * DM];   // residual stream
__device__ __align__(16) float g_xn   [MT * DM];   // layernorm output
__device__ __align__(16) float g_xp   [MT * DI];   // inproj half 1
__device__ __align__(16) float g_z    [MT * DI];   // inproj half 2 (gate)
__device__ __align__(16) float g_xc   [MT * DI];   // conv+silu output
__device__ __align__(16) float g_dt   [MT * DI];   // running cumsum of dt
__device__ __align__(16) float g_y    [MT * DI];   // scan output (gated by scan3)
__device__ __align__(16) float g_Bm   [MT * DS];
__device__ __align__(16) float g_Cm   [MT * DS];
__device__ __align__(16) float g_dtraw[MT];
__device__ __align__(16) float g_hf   [BB * NCH * DS * DI];
__device__ __align__(16) float g_h0   [BB * NCH * DS * DI];

__device__ __forceinline__ float siluf(float x) {
    return x / (1.f + __expf(-x));
}

// ----------------------------------------- fused inproj + layernorm (layer 0)
__global__ void k_inln(const float* __restrict__ z,
                       const float* __restrict__ w,
                       const float* __restrict__ ipb,
                       const float* __restrict__ g,
                       const float* __restrict__ b) {
    int warp = (blockIdx.x * blockDim.x + threadIdx.x) >> 5;
    int lane = threadIdx.x & 31;
    if (warp >= MT) return;
    float4 zv = *reinterpret_cast<const float4*>(z + (size_t)warp * 4);
    float v[8];
    float s = 0.f;
#pragma unroll
    for (int i = 0; i < 8; i++) {
        int c = i * 32 + lane;
        float4 wv = *reinterpret_cast<const float4*>(w + (size_t)c * 4);
        v[i] = ipb[c] + zv.x * wv.x + zv.y * wv.y + zv.z * wv.z + zv.w * wv.w;
        g_x[(size_t)warp * DM + c] = v[i];
        s += v[i];
    }
#pragma unroll
    for (int o = 16; o; o >>= 1) s += __shfl_xor_sync(NFULL, s, o);
    float mu = s * (1.f / DM);
    float q = 0.f;
#pragma unroll
    for (int i = 0; i < 8; i++) { float d = v[i] - mu; q += d * d; }
#pragma unroll
    for (int o = 16; o; o >>= 1) q += __shfl_xor_sync(NFULL, q, o);
    float r = rsqrtf(q * (1.f / DM) + EPSV);
#pragma unroll
    for (int i = 0; i < 8; i++) {
        int c = i * 32 + lane;
        g_xn[(size_t)warp * DM + c] = (v[i] - mu) * r * g[c] + b[c];
    }
}

// ----------------------------------------------------------------- layernorm
__global__ void k_ln(const float* __restrict__ g, const float* __restrict__ b) {
    int warp = (blockIdx.x * blockDim.x + threadIdx.x) >> 5;
    int lane = threadIdx.x & 31;
    if (warp >= MT) return;
    const float* xr = g_x + (size_t)warp * DM;
    float v[8];
    float s = 0.f;
#pragma unroll
    for (int i = 0; i < 8; i++) { v[i] = xr[i * 32 + lane]; s += v[i]; }
#pragma unroll
    for (int o = 16; o; o >>= 1) s += __shfl_xor_sync(NFULL, s, o);
    float mu = s * (1.f / DM);
    float q = 0.f;
#pragma unroll
    for (int i = 0; i < 8; i++) { float d = v[i] - mu; q += d * d; }
#pragma unroll
    for (int o = 16; o; o >>= 1) q += __shfl_xor_sync(NFULL, q, o);
    float r = rsqrtf(q * (1.f / DM) + EPSV);
    float* out = g_xn + (size_t)warp * DM;
#pragma unroll
    for (int i = 0; i < 8; i++) {
        int c = i * 32 + lane;
        out[c] = (v[i] - mu) * r * g[c] + b[c];
    }
}

// ------------------------------------------------------------------- GEMM v5
// C(MT x N) = A(MT x K) * W^T. BK=16, 256 threads, double-buffered smem,
// one barrier per 16-k chunk, 2 CTAs/SM. Warp footprint 4x8 (lr2 x lcx):
// per-warp smem traffic 384B/kk (vs 576 with 16x16 grid) -> less crossbar.
// MODE 0: tile 128x128 (warps 4x2, each 32x64), 8x8 acc.
//         A=g_xn (K=256), N=1024 -> g_xp / g_z.
// MODE 1: tile 128x64 (warps 4x2, each 32x32), 8x4 acc.
//         A=g_y (gated, K=512), N=256 -> g_x += result (residual).
template <int MODE>
__global__ __launch_bounds__(256, 2)
void k_gemm(const float* __restrict__ W) {
    constexpr int K  = (MODE == 0) ? DM : DI;
    constexpr int TN = (MODE == 0) ? 128 : 64;
    constexpr int WN = TN / 2;          // warp col span: 64 or 32
    constexpr int BK = 16;
    __shared__ float As[2][BK][128];
    __shared__ float Bs[2][BK][TN];
    const int tid = threadIdx.x;
    const int mBase = blockIdx.y * 128;
    const int nBase = blockIdx.x * TN;
    const int warp = tid >> 5, lane = tid & 31;
    const int wr = warp & 3;            // warp row: 32 rows each
    const int wc = warp >> 2;           // warp col: WN cols each
    const int lr2 = lane >> 3;          // 0..3  -> rows
    const int lcx = lane & 7;           // 0..7  -> cols
    // loaders
    const int lr = tid >> 1;
    const int lc = (tid & 1) * 8;
    const int lrB = (MODE == 0) ? lr : (tid >> 2);
    const int lcB = (MODE == 0) ? lc : ((tid & 3) * 4);

    const float* Aptr = (MODE == 0) ? g_xn : g_y;
    const float* aRow = Aptr + (size_t)(mBase + lr) * K + lc;
    const float* bRow = W + (size_t)(nBase + lrB) * K + lcB;

    float4 pa0, pa1, pb0, pb1;
    auto loadAB = [&](int k0) {
        pa0 = *reinterpret_cast<const float4*>(aRow + k0);
        pa1 = *reinterpret_cast<const float4*>(aRow + k0 + 4);
        pb0 = *reinterpret_cast<const float4*>(bRow + k0);
        if (MODE == 0)
            pb1 = *reinterpret_cast<const float4*>(bRow + k0 + 4);
    };
    auto store = [&](int st) {
        As[st][lc + 0][lr] = pa0.x; As[st][lc + 1][lr] = pa0.y;
        As[st][lc + 2][lr] = pa0.z; As[st][lc + 3][lr] = pa0.w;
        As[st][lc + 4][lr] = pa1.x; As[st][lc + 5][lr] = pa1.y;
        As[st][lc + 6][lr] = pa1.z; As[st][lc + 7][lr] = pa1.w;
        Bs[st][lcB + 0][lrB] = pb0.x; Bs[st][lcB + 1][lrB] = pb0.y;
        Bs[st][lcB + 2][lrB] = pb0.z; Bs[st][lcB + 3][lrB] = pb0.w;
        if (MODE == 0) {
            Bs[st][lcB + 4][lrB] = pb1.x; Bs[st][lcB + 5][lrB] = pb1.y;
            Bs[st][lcB + 6][lrB] = pb1.z; Bs[st][lcB + 7][lrB] = pb1.w;
        }
    };

    constexpr int NJ = (MODE == 0) ? 8 : 4;
    float acc[8][NJ];
#pragma unroll
    for (int i = 0; i < 8; i++)
#pragma unroll
        for (int j = 0; j < NJ; j++) acc[i][j] = 0.f;

    loadAB(0);
    store(0);
    __syncthreads();

    const int aOff0 = wr * 32 + lr2 * 4;
    const int bOff0 = wc * WN + lcx * 4;

    for (int k0 = 0; k0 < K; k0 += BK) {
        const int cur = (k0 >> 4) & 1;
        const bool more = (k0 + BK) < K;
        if (more) loadAB(k0 + BK);
#pragma unroll
        for (int kk = 0; kk < BK; kk++) {
            float4 a0 = *reinterpret_cast<const float4*>(&As[cur][kk][aOff0]);
            float4 a1 = *reinterpret_cast<const float4*>(&As[cur][kk][aOff0 + 16]);
            const float af[8] = {a0.x, a0.y, a0.z, a0.w, a1.x, a1.y, a1.z, a1.w};
            float bf[NJ];
            {
                float4 b0 = *reinterpret_cast<const float4*>(&Bs[cur][kk][bOff0]);
                bf[0] = b0.x; bf[1] = b0.y; bf[2] = b0.z; bf[3] = b0.w;
                if (MODE == 0) {
                    float4 b1 = *reinterpret_cast<const float4*>(&Bs[cur][kk][bOff0 + 32]);
                    bf[4] = b1.x; bf[5] = b1.y; bf[6] = b1.z; bf[7] = b1.w;
                }
            }
#pragma unroll
            for (int i = 0; i < 8; i++)
#pragma unroll
                for (int j = 0; j < NJ; j++)
                    acc[i][j] = fmaf(af[i], bf[j], acc[i][j]);
        }
        if (more) store(cur ^ 1);
        __syncthreads();
    }

    // epilogue: rows mBase+wr*32+(i>>2)*16+lr2*4+(i&3);
    //           cols nBase+wc*WN+(j half)*32+lcx*4
#pragma unroll
    for (int i = 0; i < 8; i++) {
        int row = mBase + wr * 32 + (i >> 2) * 16 + lr2 * 4 + (i & 3);
#pragma unroll
        for (int jh = 0; jh < NJ / 4; jh++) {
            int n0 = nBase + wc * WN + jh * 32 + lcx * 4;
            float4 v = make_float4(acc[i][jh * 4], acc[i][jh * 4 + 1],
                                   acc[i][jh * 4 + 2], acc[i][jh * 4 + 3]);
            if (MODE == 0) {
                float* dst = (n0 < DI) ? (g_xp + (size_t)row * DI + n0)
                                       : (g_z  + (size_t)row * DI + n0 - DI);
                *reinterpret_cast<float4*>(dst) = v;
            } else {
                float4* p = reinterpret_cast<float4*>(g_x + (size_t)row * DM + n0);
                float4 o = *p;
                o.x += v.x; o.y += v.y; o.z += v.z; o.w += v.w;
                *p = o;
            }
        }
    }
}

// ---------------------------------- fused depthwise conv + SiLU + xproj GEMV
// v1 layout (proven): lane handles d = i*32+lane -> 4B coalesced accesses.
__global__ void k_cxp(const float* __restrict__ cw, const float* __restrict__ cb,
                      const float* __restrict__ Wx) {
    int warp = (blockIdx.x * blockDim.x + threadIdx.x) >> 5;
    int lane = threadIdx.x & 31;
    if (warp >= MT) return;
    const int t = warp & (SS - 1);

    float v[16];
#pragma unroll
    for (int i = 0; i < 16; i++) {
        int d = i * 32 + lane;
        float acc = cb[d];
        float4 wv = *reinterpret_cast<const float4*>(cw + (size_t)d * 4);
#pragma unroll
        for (int j = 0; j < 4; j++) {
            int tt = t - 3 + j;
            if (tt >= 0)
                acc = fmaf(g_xp[(size_t)(warp + j - 3) * DI + d], (&wv.x)[j], acc);
        }
        v[i] = siluf(acc);
        g_xc[(size_t)warp * DI + d] = v[i];
    }

    for (int n = 0; n < 2 * DS + 1; n++) {
        const float* w = Wx + (size_t)n * DI;
        float acc = 0.f;
#pragma unroll
        for (int i = 0; i < 16; i++) acc = fmaf(v[i], w[i * 32 + lane], acc);
#pragma unroll
        for (int o = 16; o; o >>= 1) acc += __shfl_xor_sync(NFULL, acc, o);
        if (lane == 0) {
            if (n < DS)          g_Bm[(size_t)warp * DS + n] = acc;
            else if (n < 2 * DS) g_Cm[(size_t)warp * DS + n - DS] = acc;
            else                 g_dtraw[warp] = acc;
        }
    }
}

// w^(s+1) powers via multiply tree
__device__ __forceinline__ void powers16(float w, float* p) {
    p[0] = w;
    p[1] = w * w;
    p[2] = p[1] * w;    p[3]  = p[1] * p[1];
    p[4] = p[3] * w;    p[5]  = p[3] * p[1];
    p[6] = p[3] * p[2]; p[7]  = p[3] * p[3];
    p[8] = p[7] * w;    p[9]  = p[7] * p[1];
    p[10] = p[7] * p[2]; p[11] = p[7] * p[3];
    p[12] = p[7] * p[4]; p[13] = p[7] * p[5];
    p[14] = p[7] * p[6]; p[15] = p[7] * p[7];
}

// ------------------------------------------- scan phase 1: per-chunk scan
// fast softplus: w = exp(-softplus(xr)) = 1/(1+exp(xr)); dtv = -log(w)
__global__ __launch_bounds__(128)
void k_scan1(const float* __restrict__ dw, const float* __restrict__ db) {
    __shared__ float Bs[CL * DS], Cs[CL * DS], dts[CL];
    const int d = blockIdx.x * 128 + threadIdx.x;
    const int c = blockIdx.y, b = blockIdx.z;
    const int tid = threadIdx.x;
    const size_t baseT = (size_t)b * SS + c * CL;

    const float4* Bsrc = reinterpret_cast<const float4*>(g_Bm + baseT * DS);
    const float4* Csrc = reinterpret_cast<const float4*>(g_Cm + baseT * DS);
#pragma unroll
    for (int i = 0; i < CL * DS / 4 / 128; i++) {
        reinterpret_cast<float4*>(Bs)[tid + i * 128] = Bsrc[tid + i * 128];
        reinterpret_cast<float4*>(Cs)[tid + i * 128] = Csrc[tid + i * 128];
    }
    if (tid < CL / 4)
        reinterpret_cast<float4*>(dts)[tid] =
            reinterpret_cast<const float4*>(g_dtraw + baseT)[tid];
    __syncthreads();

    const float dwv = dw[d], dbv = db[d];
    float h[DS];
#pragma unroll
    for (int s = 0; s < DS; s++) h[s] = 0.f;
    float cum = 0.f;

    for (int t = 0; t < CL; t++) {
        float xr = dts[t] * dwv + dbv;
        xr = fminf(fmaxf(xr, -30.f), 30.f);
        float e = __expf(xr);
        float w = __frcp_rn(1.f + e);      // exp(-dt)
        float dtv = -__logf(w);            // softplus(xr)
        float x = g_xc[(baseT + t) * DI + d];
        cum += dtv;
        g_dt[(baseT + t) * DI + d] = cum;
        float u = dtv * x;
        float p[DS];
        powers16(w, p);
        float y = 0.f;
#pragma unroll
        for (int s = 0; s < DS; s++) {
            h[s] = fmaf(h[s], p[s], u * Bs[t * DS + s]);
            y = fmaf(h[s], Cs[t * DS + s], y);
        }
        g_y[(baseT + t) * DI + d] = y;
    }
#pragma unroll
    for (int s = 0; s < DS; s++)
        g_hf[((size_t)(b * NCH + c) * DS + s) * DI + d] = h[s];
}

// ------------------------------------------- scan phase 2: chain chunk states
__global__ void k_scan2() {
    int idx = blockIdx.x * blockDim.x + threadIdx.x;
    if (idx >= BB * DS * DI) return;
    const int d = idx % DI;
    const int s = (idx / DI) % DS;
    const int b = idx / (DI * DS);
    float h = 0.f;
    const float sf = (float)(s + 1);
    for (int c = 0; c < NCH; c++) {
        size_t o = ((size_t)(b * NCH + c) * DS + s) * DI + d;
        g_h0[o] = h;
        float cumt = g_dt[((size_t)b * SS + c * CL + CL - 1) * DI + d];
        h = fmaf(__expf(-sf * cumt), h, g_hf[o]);
    }
}

// --------------------- scan phase 3: h0 correction + SiLU gating (in place)
__global__ __launch_bounds__(128)
void k_scan3() {
    __shared__ float Cs[CL * DS];
    const int c = blockIdx.y;
    const int d = blockIdx.x * 128 + threadIdx.x;
    const int b = blockIdx.z;
    const int tid = threadIdx.x;
    const size_t baseT = (size_t)b * SS + c * CL;

    if (c > 0) {
        const float4* Csrc = reinterpret_cast<const float4*>(g_Cm + baseT * DS);
#pragma unroll
        for (int i = 0; i < CL * DS / 4 / 128; i++)
            reinterpret_cast<float4*>(Cs)[tid + i * 128] = Csrc[tid + i * 128];
        __syncthreads();

        float h0[DS];
#pragma unroll
        for (int s = 0; s < DS; s++)
            h0[s] = g_h0[((size_t)(b * NCH + c) * DS + s) * DI + d];

        for (int t = 0; t < CL; t++) {
            size_t idx = (baseT + t) * DI + d;
            float cum = g_dt[idx];
            float w = __expf(-cum);
            float p[DS];
            powers16(w, p);
            float y = g_y[idx];
#pragma unroll
            for (int s = 0; s < DS; s++)
                y = fmaf(h0[s] * p[s], Cs[t * DS + s], y);
            g_y[idx] = y * siluf(g_z[idx]);
        }
    } else {
        for (int t = 0; t < CL; t++) {
            size_t idx = (baseT + t) * DI + d;
            g_y[idx] = g_y[idx] * siluf(g_z[idx]);
        }
    }
}

// ---------------------------------------------------------- final LN + head
__global__ void k_final(const float* __restrict__ g, const float* __restrict__ b,
                        const float* __restrict__ ow, const float* __restrict__ ob,
                        float* __restrict__ out) {
    int warp = (blockIdx.x * blockDim.x + threadIdx.x) >> 5;
    int lane = threadIdx.x & 31;
    if (warp >= MT) return;
    const float* xr = g_x + (size_t)warp * DM;
    float v[8];
    float s = 0.f;
#pragma unroll
    for (int i = 0; i < 8; i++) { v[i] = xr[i * 32 + lane]; s += v[i]; }
#pragma unroll
    for (int o = 16; o; o >>= 1) s += __shfl_xor_sync(NFULL, s, o);
    float mu = s * (1.f / DM);
    float q = 0.f;
#pragma unroll
    for (int i = 0; i < 8; i++) { float d = v[i] - mu; q += d * d; }
#pragma unroll
    for (int o = 16; o; o >>= 1) q += __shfl_xor_sync(NFULL, q, o);
    float r = rsqrtf(q * (1.f / DM) + EPSV);
    float a0 = 0.f, a1 = 0.f;
#pragma unroll
    for (int i = 0; i < 8; i++) {
        int c = i * 32 + lane;
        float xn = (v[i] - mu) * r * g[c] + b[c];
        a0 += xn * ow[c];
        a1 += xn * ow[DM + c];
    }
#pragma unroll
    for (int o = 16; o; o >>= 1) {
        a0 += __shfl_xor_sync(NFULL, a0, o);
        a1 += __shfl_xor_sync(NFULL, a1, o);
    }
    if (lane == 0) {
        out[(size_t)warp * 2 + 0] = a0 + ob[0];
        out[(size_t)warp * 2 + 1] = a1 + ob[1];
    }
}

// ---------------------------------------------------------------------------
extern "C" void kernel_launch(void* const* d_in, const int* in_sizes, int n_in,
                              void* d_out, int out_size) {
    (void)in_sizes; (void)n_in; (void)out_size;
    const float* z_seq     = (const float*)d_in[0];
    const float* ip_w      = (const float*)d_in[1];
    const float* ip_b      = (const float*)d_in[2];
    const float* norm_g    = (const float*)d_in[3];
    const float* norm_b    = (const float*)d_in[4];
    const float* inproj_w  = (const float*)d_in[5];
    const float* conv_w    = (const float*)d_in[6];
    const float* conv_b    = (const float*)d_in[7];
    const float* xproj_w   = (const float*)d_in[8];
    const float* dt_w      = (const float*)d_in[9];
    const float* dt_b      = (const float*)d_in[10];
    const float* outproj_w = (const float*)d_in[11];
    const float* onorm_g   = (const float*)d_in[12];
    const float* onorm_b   = (const float*)d_in[13];
    const float* op_w      = (const float*)d_in[14];
    const float* op_b      = (const float*)d_in[15];
    float* out = (float*)d_out;

    k_inln<<<MT / 8, 256>>>(z_seq, ip_w, ip_b, norm_g, norm_b);   // launch 1

    for (int l = 0; l < 2; l++) {
        if (l > 0)
            k_ln<<<MT / 8, 256>>>(norm_g + l * DM, norm_b + l * DM);
        k_gemm<0><<<dim3(2 * DI / 128, MT / 128), 256>>>(         // l=0: launch 2
            inproj_w + (size_t)l * 2 * DI * DM);
        k_cxp<<<MT / 8, 256>>>(conv_w + (size_t)l * DI * 4,       // l=0: launch 3
                               conv_b + (size_t)l * DI,
                               xproj_w + (size_t)l * (2 * DS + 1) * DI);
        k_scan1<<<dim3(DI / 128, NCH, BB), 128>>>(dt_w + (size_t)l * DI,  // l=0: launch 4
                                                  dt_b + (size_t)l * DI);
        k_scan2<<<BB * DS * DI / 256, 256>>>();
        k_scan3<<<dim3(DI / 128, NCH, BB), 128>>>();
        k_gemm<1><<<dim3(DM / 64, MT / 128), 256>>>(
            outproj_w + (size_t)l * DM * DI);
    }

    k_final<<<MT / 8, 256>>>(onorm_g, onorm_b, op_w, op_b, out);
}

// round 11
// speedup vs baseline: 1.3220x; 1.0490x over previous
#include <cuda_runtime.h>
#include <cstdint>

#define NFULL 0xffffffffu

namespace {
constexpr int BB   = 8;
constexpr int SS   = 4096;
constexpr int DM   = 256;
constexpr int DI   = 512;
constexpr int DS   = 16;
constexpr int MT   = BB * SS;   // 32768 tokens
constexpr int NCH  = 64;        // scan chunks
constexpr int CL   = SS / NCH;  // 64 steps per chunk
constexpr float EPSV = 1e-5f;
}

// ------------------------------------------------------------------ scratch
__device__ __align__(16) float g_x    [MT * DM];   // residual stream
__device__ __align__(16) float g_xn   [MT * DM];   // layernorm output
__device__ __align__(16) float g_xp   [MT * DI];   // inproj half 1
__device__ __align__(16) float g_z    [MT * DI];   // inproj half 2 (gate)
__device__ __align__(16) float g_xc   [MT * DI];   // conv+silu output
__device__ __align__(16) float g_y    [MT * DI];   // scan output (gated by scan3)
__device__ __align__(16) float g_Bm   [MT * DS];
__device__ __align__(16) float g_Cm   [MT * DS];
__device__ __align__(16) float g_dtraw[MT];
__device__ __align__(16) float g_cumf [BB * NCH * DI];       // chunk-final cumsum
__device__ __align__(16) float g_hf   [BB * NCH * DS * DI];
__device__ __align__(16) float g_h0   [BB * NCH * DS * DI];

__device__ __forceinline__ float siluf(float x) {
    return x / (1.f + __expf(-x));
}

// ----------------------------------------- fused inproj + layernorm (layer 0)
__global__ void k_inln(const float* __restrict__ z,
                       const float* __restrict__ w,
                       const float* __restrict__ ipb,
                       const float* __restrict__ g,
                       const float* __restrict__ b) {
    int warp = (blockIdx.x * blockDim.x + threadIdx.x) >> 5;
    int lane = threadIdx.x & 31;
    if (warp >= MT) return;
    float4 zv = *reinterpret_cast<const float4*>(z + (size_t)warp * 4);
    float v[8];
    float s = 0.f;
#pragma unroll
    for (int i = 0; i < 8; i++) {
        int c = i * 32 + lane;
        float4 wv = *reinterpret_cast<const float4*>(w + (size_t)c * 4);
        v[i] = ipb[c] + zv.x * wv.x + zv.y * wv.y + zv.z * wv.z + zv.w * wv.w;
        g_x[(size_t)warp * DM + c] = v[i];
        s += v[i];
    }
#pragma unroll
    for (int o = 16; o; o >>= 1) s += __shfl_xor_sync(NFULL, s, o);
    float mu = s * (1.f / DM);
    float q = 0.f;
#pragma unroll
    for (int i = 0; i < 8; i++) { float d = v[i] - mu; q += d * d; }
#pragma unroll
    for (int o = 16; o; o >>= 1) q += __shfl_xor_sync(NFULL, q, o);
    float r = rsqrtf(q * (1.f / DM) + EPSV);
#pragma unroll
    for (int i = 0; i < 8; i++) {
        int c = i * 32 + lane;
        g_xn[(size_t)warp * DM + c] = (v[i] - mu) * r * g[c] + b[c];
    }
}

// ----------------------------------------------------------------- layernorm
__global__ void k_ln(const float* __restrict__ g, const float* __restrict__ b) {
    int warp = (blockIdx.x * blockDim.x + threadIdx.x) >> 5;
    int lane = threadIdx.x & 31;
    if (warp >= MT) return;
    const float* xr = g_x + (size_t)warp * DM;
    float v[8];
    float s = 0.f;
#pragma unroll
    for (int i = 0; i < 8; i++) { v[i] = xr[i * 32 + lane]; s += v[i]; }
#pragma unroll
    for (int o = 16; o; o >>= 1) s += __shfl_xor_sync(NFULL, s, o);
    float mu = s * (1.f / DM);
    float q = 0.f;
#pragma unroll
    for (int i = 0; i < 8; i++) { float d = v[i] - mu; q += d * d; }
#pragma unroll
    for (int o = 16; o; o >>= 1) q += __shfl_xor_sync(NFULL, q, o);
    float r = rsqrtf(q * (1.f / DM) + EPSV);
    float* out = g_xn + (size_t)warp * DM;
#pragma unroll
    for (int i = 0; i < 8; i++) {
        int c = i * 32 + lane;
        out[c] = (v[i] - mu) * r * g[c] + b[c];
    }
}

// ------------------------------------------------------------------- GEMM v5
// C(MT x N) = A(MT x K) * W^T. BK=16, 256 threads, double-buffered smem,
// one barrier per 16-k chunk, 2 CTAs/SM.
// MODE 0: tile 128x128, A=g_xn (K=256), N=1024 -> g_xp / g_z.
// MODE 1: tile 128x64, A=g_y (gated, K=512), N=256 -> g_x += (residual).
template <int MODE>
__global__ __launch_bounds__(256, 2)
void k_gemm(const float* __restrict__ W) {
    constexpr int K  = (MODE == 0) ? DM : DI;
    constexpr int TN = (MODE == 0) ? 128 : 64;
    constexpr int WN = TN / 2;
    constexpr int BK = 16;
    __shared__ float As[2][BK][128];
    __shared__ float Bs[2][BK][TN];
    const int tid = threadIdx.x;
    const int mBase = blockIdx.y * 128;
    const int nBase = blockIdx.x * TN;
    const int warp = tid >> 5, lane = tid & 31;
    const int wr = warp & 3;
    const int wc = warp >> 2;
    const int lr2 = lane >> 3;
    const int lcx = lane & 7;
    const int lr = tid >> 1;
    const int lc = (tid & 1) * 8;
    const int lrB = (MODE == 0) ? lr : (tid >> 2);
    const int lcB = (MODE == 0) ? lc : ((tid & 3) * 4);

    const float* Aptr = (MODE == 0) ? g_xn : g_y;
    const float* aRow = Aptr + (size_t)(mBase + lr) * K + lc;
    const float* bRow = W + (size_t)(nBase + lrB) * K + lcB;

    float4 pa0, pa1, pb0, pb1;
    auto loadAB = [&](int k0) {
        pa0 = *reinterpret_cast<const float4*>(aRow + k0);
        pa1 = *reinterpret_cast<const float4*>(aRow + k0 + 4);
        pb0 = *reinterpret_cast<const float4*>(bRow + k0);
        if (MODE == 0)
            pb1 = *reinterpret_cast<const float4*>(bRow + k0 + 4);
    };
    auto store = [&](int st) {
        As[st][lc + 0][lr] = pa0.x; As[st][lc + 1][lr] = pa0.y;
        As[st][lc + 2][lr] = pa0.z; As[st][lc + 3][lr] = pa0.w;
        As[st][lc + 4][lr] = pa1.x; As[st][lc + 5][lr] = pa1.y;
        As[st][lc + 6][lr] = pa1.z; As[st][lc + 7][lr] = pa1.w;
        Bs[st][lcB + 0][lrB] = pb0.x; Bs[st][lcB + 1][lrB] = pb0.y;
        Bs[st][lcB + 2][lrB] = pb0.z; Bs[st][lcB + 3][lrB] = pb0.w;
        if (MODE == 0) {
            Bs[st][lcB + 4][lrB] = pb1.x; Bs[st][lcB + 5][lrB] = pb1.y;
            Bs[st][lcB + 6][lrB] = pb1.z; Bs[st][lcB + 7][lrB] = pb1.w;
        }
    };

    constexpr int NJ = (MODE == 0) ? 8 : 4;
    float acc[8][NJ];
#pragma unroll
    for (int i = 0; i < 8; i++)
#pragma unroll
        for (int j = 0; j < NJ; j++) acc[i][j] = 0.f;

    loadAB(0);
    store(0);
    __syncthreads();

    const int aOff0 = wr * 32 + lr2 * 4;
    const int bOff0 = wc * WN + lcx * 4;

    for (int k0 = 0; k0 < K; k0 += BK) {
        const int cur = (k0 >> 4) & 1;
        const bool more = (k0 + BK) < K;
        if (more) loadAB(k0 + BK);
#pragma unroll
        for (int kk = 0; kk < BK; kk++) {
            float4 a0 = *reinterpret_cast<const float4*>(&As[cur][kk][aOff0]);
            float4 a1 = *reinterpret_cast<const float4*>(&As[cur][kk][aOff0 + 16]);
            const float af[8] = {a0.x, a0.y, a0.z, a0.w, a1.x, a1.y, a1.z, a1.w};
            float bf[NJ];
            {
                float4 b0 = *reinterpret_cast<const float4*>(&Bs[cur][kk][bOff0]);
                bf[0] = b0.x; bf[1] = b0.y; bf[2] = b0.z; bf[3] = b0.w;
                if (MODE == 0) {
                    float4 b1 = *reinterpret_cast<const float4*>(&Bs[cur][kk][bOff0 + 32]);
                    bf[4] = b1.x; bf[5] = b1.y; bf[6] = b1.z; bf[7] = b1.w;
                }
            }
#pragma unroll
            for (int i = 0; i < 8; i++)
#pragma unroll
                for (int j = 0; j < NJ; j++)
                    acc[i][j] = fmaf(af[i], bf[j], acc[i][j]);
        }
        if (more) store(cur ^ 1);
        __syncthreads();
    }

#pragma unroll
    for (int i = 0; i < 8; i++) {
        int row = mBase + wr * 32 + (i >> 2) * 16 + lr2 * 4 + (i & 3);
#pragma unroll
        for (int jh = 0; jh < NJ / 4; jh++) {
            int n0 = nBase + wc * WN + jh * 32 + lcx * 4;
            float4 v = make_float4(acc[i][jh * 4], acc[i][jh * 4 + 1],
                                   acc[i][jh * 4 + 2], acc[i][jh * 4 + 3]);
            if (MODE == 0) {
                float* dst = (n0 < DI) ? (g_xp + (size_t)row * DI + n0)
                                       : (g_z  + (size_t)row * DI + n0 - DI);
                *reinterpret_cast<float4*>(dst) = v;
            } else {
                float4* p = reinterpret_cast<float4*>(g_x + (size_t)row * DM + n0);
                float4 o = *p;
                o.x += v.x; o.y += v.y; o.z += v.z; o.w += v.w;
                *p = o;
            }
        }
    }
}

// ---------------------------------- fused depthwise conv + SiLU + xproj GEMV
__global__ void k_cxp(const float* __restrict__ cw, const float* __restrict__ cb,
                      const float* __restrict__ Wx) {
    int warp = (blockIdx.x * blockDim.x + threadIdx.x) >> 5;
    int lane = threadIdx.x & 31;
    if (warp >= MT) return;
    const int t = warp & (SS - 1);

    float v[16];
#pragma unroll
    for (int i = 0; i < 16; i++) {
        int d = i * 32 + lane;
        float acc = cb[d];
        float4 wv = *reinterpret_cast<const float4*>(cw + (size_t)d * 4);
#pragma unroll
        for (int j = 0; j < 4; j++) {
            int tt = t - 3 + j;
            if (tt >= 0)
                acc = fmaf(g_xp[(size_t)(warp + j - 3) * DI + d], (&wv.x)[j], acc);
        }
        v[i] = siluf(acc);
        g_xc[(size_t)warp * DI + d] = v[i];
    }

#pragma unroll
    for (int n = 0; n < 2 * DS + 1; n++) {
        const float* w = Wx + (size_t)n * DI;
        float acc = 0.f;
#pragma unroll
        for (int i = 0; i < 16; i++) acc = fmaf(v[i], w[i * 32 + lane], acc);
#pragma unroll
        for (int o = 16; o; o >>= 1) acc += __shfl_xor_sync(NFULL, acc, o);
        if (lane == 0) {
            if (n < DS)          g_Bm[(size_t)warp * DS + n] = acc;
            else if (n < 2 * DS) g_Cm[(size_t)warp * DS + n - DS] = acc;
            else                 g_dtraw[warp] = acc;
        }
    }
}

// w^(s+1) powers via multiply tree
__device__ __forceinline__ void powers16(float w, float* p) {
    p[0] = w;
    p[1] = w * w;
    p[2] = p[1] * w;    p[3]  = p[1] * p[1];
    p[4] = p[3] * w;    p[5]  = p[3] * p[1];
    p[6] = p[3] * p[2]; p[7]  = p[3] * p[3];
    p[8] = p[7] * w;    p[9]  = p[7] * p[1];
    p[10] = p[7] * p[2]; p[11] = p[7] * p[3];
    p[12] = p[7] * p[4]; p[13] = p[7] * p[5];
    p[14] = p[7] * p[6]; p[15] = p[7] * p[7];
}

// ------------------------------------------- scan phase 1: per-chunk scan
// fast softplus: w = exp(-softplus(xr)) = 1/(1+exp(xr)); dtv = -log(w).
// No per-element cumsum store; only chunk-final cum -> g_cumf.
__global__ __launch_bounds__(128)
void k_scan1(const float* __restrict__ dw, const float* __restrict__ db) {
    __shared__ float Bs[CL * DS], Cs[CL * DS], dts[CL];
    const int d = blockIdx.x * 128 + threadIdx.x;
    const int c = blockIdx.y, b = blockIdx.z;
    const int tid = threadIdx.x;
    const size_t baseT = (size_t)b * SS + c * CL;

    const float4* Bsrc = reinterpret_cast<const float4*>(g_Bm + baseT * DS);
    const float4* Csrc = reinterpret_cast<const float4*>(g_Cm + baseT * DS);
#pragma unroll
    for (int i = 0; i < CL * DS / 4 / 128; i++) {
        reinterpret_cast<float4*>(Bs)[tid + i * 128] = Bsrc[tid + i * 128];
        reinterpret_cast<float4*>(Cs)[tid + i * 128] = Csrc[tid + i * 128];
    }
    if (tid < CL / 4)
        reinterpret_cast<float4*>(dts)[tid] =
            reinterpret_cast<const float4*>(g_dtraw + baseT)[tid];
    __syncthreads();

    const float dwv = dw[d], dbv = db[d];
    float h[DS];
#pragma unroll
    for (int s = 0; s < DS; s++) h[s] = 0.f;
    float cum = 0.f;

    float xnext = g_xc[baseT * DI + d];
    for (int t = 0; t < CL; t++) {
        float x = xnext;
        if (t + 1 < CL) xnext = g_xc[(baseT + t + 1) * DI + d];
        float xr = dts[t] * dwv + dbv;
        xr = fminf(fmaxf(xr, -30.f), 30.f);
        float e = __expf(xr);
        float w = __frcp_rn(1.f + e);      // exp(-dt)
        float dtv = -__logf(w);            // softplus(xr)
        cum += dtv;
        float u = dtv * x;
        float p[DS];
        powers16(w, p);
        float y = 0.f;
#pragma unroll
        for (int s = 0; s < DS; s++) {
            h[s] = fmaf(h[s], p[s], u * Bs[t * DS + s]);
            y = fmaf(h[s], Cs[t * DS + s], y);
        }
        g_y[(baseT + t) * DI + d] = y;
    }
    g_cumf[((size_t)(b * NCH + c)) * DI + d] = cum;
#pragma unroll
    for (int s = 0; s < DS; s++)
        g_hf[((size_t)(b * NCH + c) * DS + s) * DI + d] = h[s];
}

// ------------------------------------------- scan phase 2: chain chunk states
__global__ void k_scan2() {
    int idx = blockIdx.x * blockDim.x + threadIdx.x;
    if (idx >= BB * DS * DI) return;
    const int d = idx % DI;
    const int s = (idx / DI) % DS;
    const int b = idx / (DI * DS);
    float h = 0.f;
    const float sf = (float)(s + 1);
    for (int c = 0; c < NCH; c++) {
        size_t o = ((size_t)(b * NCH + c) * DS + s) * DI + d;
        g_h0[o] = h;
        float cumt = g_cumf[((size_t)(b * NCH + c)) * DI + d];
        h = fmaf(__expf(-sf * cumt), h, g_hf[o]);
    }
}

// --------------------- scan phase 3: h0 correction + SiLU gating (in place)
// Recomputes exp(-cum_t) multiplicatively from staged dtraw (no g_dt stream).
__global__ __launch_bounds__(128)
void k_scan3(const float* __restrict__ dw, const float* __restrict__ db) {
    __shared__ float Cs[CL * DS], dts[CL];
    const int c = blockIdx.y;
    const int d = blockIdx.x * 128 + threadIdx.x;
    const int b = blockIdx.z;
    const int tid = threadIdx.x;
    const size_t baseT = (size_t)b * SS + c * CL;

    if (c > 0) {
        const float4* Csrc = reinterpret_cast<const float4*>(g_Cm + baseT * DS);
#pragma unroll
        for (int i = 0; i < CL * DS / 4 / 128; i++)
            reinterpret_cast<float4*>(Cs)[tid + i * 128] = Csrc[tid + i * 128];
        if (tid < CL / 4)
            reinterpret_cast<float4*>(dts)[tid] =
                reinterpret_cast<const float4*>(g_dtraw + baseT)[tid];
        __syncthreads();

        const float dwv = dw[d], dbv = db[d];
        float h0[DS];
#pragma unroll
        for (int s = 0; s < DS; s++)
            h0[s] = g_h0[((size_t)(b * NCH + c) * DS + s) * DI + d];

        float wcum = 1.f;
        for (int t = 0; t < CL; t++) {
            size_t idx = (baseT + t) * DI + d;
            float xr = dts[t] * dwv + dbv;
            xr = fminf(fmaxf(xr, -30.f), 30.f);
            float e = __expf(xr);
            wcum *= __frcp_rn(1.f + e);    // *= exp(-dt_t)
            float p[DS];
            powers16(wcum, p);
            float y = g_y[idx];
#pragma unroll
            for (int s = 0; s < DS; s++)
                y = fmaf(h0[s] * p[s], Cs[t * DS + s], y);
            g_y[idx] = y * siluf(g_z[idx]);
        }
    } else {
        for (int t = 0; t < CL; t++) {
            size_t idx = (baseT + t) * DI + d;
            g_y[idx] = g_y[idx] * siluf(g_z[idx]);
        }
    }
}

// ---------------------------------------------------------- final LN + head
__global__ void k_final(const float* __restrict__ g, const float* __restrict__ b,
                        const float* __restrict__ ow, const float* __restrict__ ob,
                        float* __restrict__ out) {
    int warp = (blockIdx.x * blockDim.x + threadIdx.x) >> 5;
    int lane = threadIdx.x & 31;
    if (warp >= MT) return;
    const float* xr = g_x + (size_t)warp * DM;
    float v[8];
    float s = 0.f;
#pragma unroll
    for (int i = 0; i < 8; i++) { v[i] = xr[i * 32 + lane]; s += v[i]; }
#pragma unroll
    for (int o = 16; o; o >>= 1) s += __shfl_xor_sync(NFULL, s, o);
    float mu = s * (1.f / DM);
    float q = 0.f;
#pragma unroll
    for (int i = 0; i < 8; i++) { float d = v[i] - mu; q += d * d; }
#pragma unroll
    for (int o = 16; o; o >>= 1) q += __shfl_xor_sync(NFULL, q, o);
    float r = rsqrtf(q * (1.f / DM) + EPSV);
    float a0 = 0.f, a1 = 0.f;
#pragma unroll
    for (int i = 0; i < 8; i++) {
        int c = i * 32 + lane;
        float xn = (v[i] - mu) * r * g[c] + b[c];
        a0 += xn * ow[c];
        a1 += xn * ow[DM + c];
    }
#pragma unroll
    for (int o = 16; o; o >>= 1) {
        a0 += __shfl_xor_sync(NFULL, a0, o);
        a1 += __shfl_xor_sync(NFULL, a1, o);
    }
    if (lane == 0) {
        out[(size_t)warp * 2 + 0] = a0 + ob[0];
        out[(size_t)warp * 2 + 1] = a1 + ob[1];
    }
}

// ---------------------------------------------------------------------------
extern "C" void kernel_launch(void* const* d_in, const int* in_sizes, int n_in,
                              void* d_out, int out_size) {
    (void)in_sizes; (void)n_in; (void)out_size;
    const float* z_seq     = (const float*)d_in[0];
    const float* ip_w      = (const float*)d_in[1];
    const float* ip_b      = (const float*)d_in[2];
    const float* norm_g    = (const float*)d_in[3];
    const float* norm_b    = (const float*)d_in[4];
    const float* inproj_w  = (const float*)d_in[5];
    const float* conv_w    = (const float*)d_in[6];
    const float* conv_b    = (const float*)d_in[7];
    const float* xproj_w   = (const float*)d_in[8];
    const float* dt_w      = (const float*)d_in[9];
    const float* dt_b      = (const float*)d_in[10];
    const float* outproj_w = (const float*)d_in[11];
    const float* onorm_g   = (const float*)d_in[12];
    const float* onorm_b   = (const float*)d_in[13];
    const float* op_w      = (const float*)d_in[14];
    const float* op_b      = (const float*)d_in[15];
    float* out = (float*)d_out;

    k_inln<<<MT / 8, 256>>>(z_seq, ip_w, ip_b, norm_g, norm_b);   // launch 1

    for (int l = 0; l < 2; l++) {
        if (l > 0)
            k_ln<<<MT / 8, 256>>>(norm_g + l * DM, norm_b + l * DM);
        k_gemm<0><<<dim3(2 * DI / 128, MT / 128), 256>>>(         // l=0: launch 2
            inproj_w + (size_t)l * 2 * DI * DM);
        k_cxp<<<MT / 8, 256>>>(conv_w + (size_t)l * DI * 4,       // l=0: launch 3
                               conv_b + (size_t)l * DI,
                               xproj_w + (size_t)l * (2 * DS + 1) * DI);
        k_scan1<<<dim3(DI / 128, NCH, BB), 128>>>(dt_w + (size_t)l * DI,  // l=0: launch 4
                                                  dt_b + (size_t)l * DI);
        k_scan2<<<BB * DS * DI / 256, 256>>>();
        k_scan3<<<dim3(DI / 128, NCH, BB), 128>>>(dt_w + (size_t)l * DI,
                                                  dt_b + (size_t)l * DI);
        k_gemm<1><<<dim3(DM / 64, MT / 128), 256>>>(
            outproj_w + (size_t)l * DM * DI);
    }

    k_final<<<MT / 8, 256>>>(onorm_g, onorm_b, op_w, op_b, out);
}